// round 15
// baseline (speedup 1.0000x reference)
#include <cuda_runtime.h>
#include <cstdint>

#define Bc 2
#define Sc 2048
#define Dc 1024
#define Hc 16
#define HDc 64
#define BHc (Bc*Hc)
#define SCALEc 0.125f              // 64^-0.5
#define KLOG2 0.1803368801111243f // SCALEc * log2(e)

// ---- scratch (allocation-free rule: __device__ globals) --------------------
__device__ float g_Q[(size_t)Bc * Sc * Dc];
__device__ float g_K[(size_t)Bc * Sc * Dc];
__device__ float g_V[(size_t)Bc * Sc * Dc];
__device__ float g_ctx[(size_t)Bc * Sc * Dc];
__device__ float g_invsum[(size_t)BHc * Sc];
// pre-rounded (tf32) copies of inputs + weights
__device__ float g_qin[(size_t)Bc * Sc * Dc];
__device__ float g_kin[(size_t)Bc * Sc * Dc];
__device__ float g_vin[(size_t)Bc * Sc * Dc];
__device__ float g_wq[(size_t)Dc * Dc];
__device__ float g_wk[(size_t)Dc * Dc];
__device__ float g_wv[(size_t)Dc * Dc];
__device__ float g_wo[(size_t)Dc * Dc];
__device__ float g_attn_fb[(size_t)BHc * Sc * Sc];   // fallback if out only holds `output`

// ---- helpers ----------------------------------------------------------------
__device__ __forceinline__ float tf32_round(float x) {
    return __uint_as_float((__float_as_uint(x) + 0x1000u) & 0xFFFFE000u);
}
__device__ __forceinline__ uint32_t f2tf(float x) {
    uint32_t r; asm("cvt.rna.tf32.f32 %0, %1;" : "=r"(r) : "f"(x)); return r;
}
__device__ __forceinline__ float ex2(float x) {
    float r; asm("ex2.approx.f32 %0, %1;" : "=f"(r) : "f"(x)); return r;
}
__device__ __forceinline__ void mma8(float* d, const uint32_t* a, const uint32_t* b) {
    asm volatile(
        "mma.sync.aligned.m16n8k8.row.col.f32.tf32.tf32.f32 "
        "{%0,%1,%2,%3}, {%4,%5,%6,%7}, {%8,%9}, {%0,%1,%2,%3};\n"
        : "+f"(d[0]), "+f"(d[1]), "+f"(d[2]), "+f"(d[3])
        : "r"(a[0]), "r"(a[1]), "r"(a[2]), "r"(a[3]), "r"(b[0]), "r"(b[1]));
}
__device__ __forceinline__ uint32_t smem_u32(const void* p) {
    uint32_t r;
    asm("{ .reg .u64 t; cvta.to.shared.u64 t, %1; cvt.u32.u64 %0, t; }"
        : "=r"(r) : "l"(p));
    return r;
}
__device__ __forceinline__ void cpa16(uint32_t saddr, const void* g) {
    asm volatile("cp.async.cg.shared.global [%0], [%1], 16;" :: "r"(saddr), "l"(g));
}
__device__ __forceinline__ void cpa_commit() { asm volatile("cp.async.commit_group;"); }
__device__ __forceinline__ void cpa_wait0()  { asm volatile("cp.async.wait_group 0;"); }
__device__ __forceinline__ void cpa_wait1()  { asm volatile("cp.async.wait_group 1;"); }

// ============================================================================
// prep: round inputs + weights to tf32 (producer-side rounding).
// ============================================================================
__global__ __launch_bounds__(256)
void prep_round(const float4* __restrict__ q, const float4* __restrict__ k,
                const float4* __restrict__ v,
                const float4* __restrict__ wq, const float4* __restrict__ wk,
                const float4* __restrict__ wv, const float4* __restrict__ wo,
                float4* __restrict__ oq, float4* __restrict__ ok,
                float4* __restrict__ ov,
                float4* __restrict__ owq, float4* __restrict__ owk,
                float4* __restrict__ owv, float4* __restrict__ owo) {
    const float4* src; float4* dst; size_t n4;
    const size_t NIN = (size_t)Bc * Sc * Dc / 4;
    const size_t NW  = (size_t)Dc * Dc / 4;
    switch (blockIdx.z) {
        case 0: src = q;  dst = oq;  n4 = NIN; break;
        case 1: src = k;  dst = ok;  n4 = NIN; break;
        case 2: src = v;  dst = ov;  n4 = NIN; break;
        case 3: src = wq; dst = owq; n4 = NW;  break;
        case 4: src = wk; dst = owk; n4 = NW;  break;
        case 5: src = wv; dst = owv; n4 = NW;  break;
        default: src = wo; dst = owo; n4 = NW;  break;
    }
    size_t i = (size_t)blockIdx.x * 256 + threadIdx.x;
    const size_t stride = (size_t)gridDim.x * 256;
    for (; i < n4; i += stride) {
        float4 t = src[i];
        t.x = tf32_round(t.x); t.y = tf32_round(t.y);
        t.z = tf32_round(t.z); t.w = tf32_round(t.w);
        dst[i] = t;
    }
}

// ============================================================================
// GEMM + bias: cp.async double-buffered, BK=16, pure-truncation tf32
// fragments (operands pre-rounded, so truncation == rna).
// ============================================================================
struct GemmSmem {
    float As[2][128][20];
    float Bs[2][16][136];
};

template<bool RND_OUT>
__device__ __forceinline__
void gemm_body(const float* __restrict__ A, const float* __restrict__ W,
               const float* __restrict__ bias, float* __restrict__ C,
               int M, int N, int K, GemmSmem& sm) {
    const int tid = threadIdx.x;
    const int lane = tid & 31, warp = tid >> 5;
    const int wm = warp >> 2, wn = warp & 3;
    const int row0 = blockIdx.y * 128, col0 = blockIdx.x * 128;
    const int r_lo = lane >> 2, c_lo = lane & 3;

    const int rowA = tid >> 1, colA = (tid & 1) * 8;
    const int rowB = tid >> 4, colB = (tid & 15) * 8;

    const uint32_t sA[2] = { smem_u32(&sm.As[0][rowA][colA]),
                             smem_u32(&sm.As[1][rowA][colA]) };
    const uint32_t sB[2] = { smem_u32(&sm.Bs[0][rowB][colB]),
                             smem_u32(&sm.Bs[1][rowB][colB]) };
    const float* gA = A + (size_t)(row0 + rowA) * K + colA;
    const float* gB = W + (size_t)rowB * N + col0 + colB;

    float acc[4][4][4] = {};

    cpa16(sA[0], gA); cpa16(sA[0] + 16, gA + 4);
    cpa16(sB[0], gB); cpa16(sB[0] + 16, gB + 4);
    cpa_commit();

    const int nk = K >> 4;
    for (int kt = 0; kt < nk; kt++) {
        const int s = kt & 1;
        if (kt + 1 < nk) {
            const float* gA2 = gA + (kt + 1) * 16;
            const float* gB2 = gB + (size_t)(kt + 1) * 16 * N;
            cpa16(sA[s ^ 1], gA2); cpa16(sA[s ^ 1] + 16, gA2 + 4);
            cpa16(sB[s ^ 1], gB2); cpa16(sB[s ^ 1] + 16, gB2 + 4);
            cpa_commit();
            cpa_wait1();
        } else {
            cpa_wait0();
        }
        __syncthreads();

        const float (*As_)[20]  = sm.As[s];
        const float (*Bs_)[136] = sm.Bs[s];
#pragma unroll
        for (int ks = 0; ks < 16; ks += 8) {
            uint32_t af[4][4], bf[4][2];
#pragma unroll
            for (int mt = 0; mt < 4; mt++) {
                int rb = wm * 64 + mt * 16 + r_lo;
                af[mt][0] = __float_as_uint(As_[rb][ks + c_lo]);
                af[mt][1] = __float_as_uint(As_[rb + 8][ks + c_lo]);
                af[mt][2] = __float_as_uint(As_[rb][ks + 4 + c_lo]);
                af[mt][3] = __float_as_uint(As_[rb + 8][ks + 4 + c_lo]);
            }
#pragma unroll
            for (int nt = 0; nt < 4; nt++) {
                int cb = wn * 32 + nt * 8 + r_lo;
                bf[nt][0] = __float_as_uint(Bs_[ks + c_lo][cb]);
                bf[nt][1] = __float_as_uint(Bs_[ks + 4 + c_lo][cb]);
            }
#pragma unroll
            for (int mt = 0; mt < 4; mt++)
#pragma unroll
                for (int nt = 0; nt < 4; nt++)
                    mma8(acc[mt][nt], af[mt], bf[nt]);
        }
        __syncthreads();
    }

#pragma unroll
    for (int mt = 0; mt < 4; mt++) {
        int row = row0 + wm * 64 + mt * 16 + r_lo;
#pragma unroll
        for (int nt = 0; nt < 4; nt++) {
            int col = col0 + wn * 32 + nt * 8 + c_lo * 2;
            float b0 = bias[col], b1 = bias[col + 1];
            float v0 = acc[mt][nt][0] + b0, v1 = acc[mt][nt][1] + b1;
            float v2 = acc[mt][nt][2] + b0, v3 = acc[mt][nt][3] + b1;
            if (RND_OUT) {
                v0 = tf32_round(v0); v1 = tf32_round(v1);
                v2 = tf32_round(v2); v3 = tf32_round(v3);
            }
            C[(size_t)row * N + col]           = v0;
            C[(size_t)row * N + col + 1]       = v1;
            C[(size_t)(row + 8) * N + col]     = v2;
            C[(size_t)(row + 8) * N + col + 1] = v3;
        }
    }
}

__global__ __launch_bounds__(256)
void gemm_bias_tc(const float* __restrict__ A, const float* __restrict__ W,
                  const float* __restrict__ bias, float* __restrict__ C,
                  int M, int N, int K) {
    __shared__ GemmSmem sm;
    gemm_body<false>(A, W, bias, C, M, N, K, sm);
}

// qkv for a row range (pointers pre-offset by caller); grid (8, rows/128, 3)
__global__ __launch_bounds__(256)
void qkv_gemm(const float* __restrict__ q, const float* __restrict__ k,
              const float* __restrict__ v,
              const float* __restrict__ Wq, const float* __restrict__ bq,
              const float* __restrict__ Wk, const float* __restrict__ bk,
              const float* __restrict__ Wv, const float* __restrict__ bv,
              float* __restrict__ Qo, float* __restrict__ Ko, float* __restrict__ Vo) {
    __shared__ GemmSmem sm;
    const float *A, *W, *bias; float* C;
    if (blockIdx.z == 0)      { A = q; W = Wq; bias = bq; C = Qo; }
    else if (blockIdx.z == 1) { A = k; W = Wk; bias = bk; C = Ko; }
    else                      { A = v; W = Wv; bias = bv; C = Vo; }
    gemm_body<true>(A, W, bias, C, Bc * Sc, Dc, Dc, sm);
}

// ============================================================================
// Fused attention — round-10 config + bh_base for half-grid pipelining.
// 512 threads (16 warps, 8m x 2n), 128 q-rows/block, double-buffered K/V.
// ============================================================================
#define FK0 0
#define FK1 8704
#define FV0 17408
#define FV1 26112
#define FRED 34816
#define FRED2 35072
#define FTOT 35200            // *4 = 140800 bytes

__global__ __launch_bounds__(512)
void fused_attn(const float* __restrict__ Qp, const float* __restrict__ Kp,
                const float* __restrict__ Vp, float* __restrict__ attn,
                float* __restrict__ invg, float* __restrict__ ctx, int bh_base) {
    extern __shared__ float smf[];
    const uint32_t sbase = smem_u32(smf);

    const int bh = bh_base + blockIdx.y, b = bh >> 4, h = bh & 15;
    const int row0 = blockIdx.x * 128;
    const float* Qh = Qp + (size_t)b * Sc * Dc + h * HDc;
    const float* Kh = Kp + (size_t)b * Sc * Dc + h * HDc;
    const float* Vh = Vp + (size_t)b * Sc * Dc + h * HDc;
    float* outp = attn + (size_t)bh * Sc * Sc;

    const int tid = threadIdx.x, lane = tid & 31, warp = tid >> 5;
    const int wm = warp >> 1, wn = warp & 1;   // 8m x 2n
    const int g = lane >> 2, c = lane & 3;

    const int ldr0 = tid >> 4;                 // rows 0..31 (+32 per i)
    const int ldc4 = (tid & 15) * 4;

    {
#pragma unroll
        for (int i = 0; i < 4; i++) {
            int r = ldr0 + i * 32;
            cpa16(sbase + (uint32_t)(FK0 + r * 68 + ldc4) * 4, Kh + (size_t)r * Dc + ldc4);
            cpa16(sbase + (uint32_t)(FV0 + r * 68 + ldc4) * 4, Vh + (size_t)r * Dc + ldc4);
        }
        cpa_commit();
    }

    // Q fragments: raw bits (Qp pre-rounded to tf32 by qkv epilogue)
    uint32_t qf[8][4];
    {
        const int qr = row0 + wm * 16;
#pragma unroll
        for (int s8 = 0; s8 < 8; s8++) {
            qf[s8][0] = __float_as_uint(Qh[(size_t)(qr + g)     * Dc + s8 * 8 + c]);
            qf[s8][1] = __float_as_uint(Qh[(size_t)(qr + g + 8) * Dc + s8 * 8 + c]);
            qf[s8][2] = __float_as_uint(Qh[(size_t)(qr + g)     * Dc + s8 * 8 + c + 4]);
            qf[s8][3] = __float_as_uint(Qh[(size_t)(qr + g + 8) * Dc + s8 * 8 + c + 4]);
        }
    }

    cpa_wait0();
    __syncthreads();

    float accU[8][4] = {};
    float rs0 = 0.f, rs1 = 0.f;

    const int src1 = (lane & ~3) | (c >> 1);
    const int src2 = src1 + 2;
    const bool odd = (c & 1);

    for (int kt = 0; kt < 16; kt++) {
        const int s = kt & 1;
        if (kt + 1 < 16) {
            const float* gk = Kh + (size_t)((kt + 1) * 128) * Dc;
            const float* gv = Vh + (size_t)((kt + 1) * 128) * Dc;
            const int KD = s ? FK0 : FK1;
            const int VD = s ? FV0 : FV1;
#pragma unroll
            for (int i = 0; i < 4; i++) {
                int r = ldr0 + i * 32;
                cpa16(sbase + (uint32_t)(KD + r * 68 + ldc4) * 4, gk + (size_t)r * Dc + ldc4);
                cpa16(sbase + (uint32_t)(VD + r * 68 + ldc4) * 4, gv + (size_t)r * Dc + ldc4);
            }
            cpa_commit();
        }
        const float* sK = smf + (s ? FK1 : FK0);
        const float* sV = smf + (s ? FV1 : FV0);
        const int k0 = kt * 128;

#pragma unroll
        for (int half = 0; half < 2; half++) {
            const int colbase = wn * 64 + half * 32;

            float accS[4][4] = {};
#pragma unroll
            for (int s8 = 0; s8 < 8; s8++) {
                uint32_t bf[4][2];
#pragma unroll
                for (int nt = 0; nt < 4; nt++) {
                    int kc = colbase + nt * 8 + g;
                    bf[nt][0] = __float_as_uint(sK[kc * 68 + s8 * 8 + c]);
                    bf[nt][1] = __float_as_uint(sK[kc * 68 + s8 * 8 + c + 4]);
                }
#pragma unroll
                for (int nt = 0; nt < 4; nt++)
                    mma8(accS[nt], qf[s8], bf[nt]);
            }

            const int grow = row0 + wm * 16 + g;
#pragma unroll
            for (int nt = 0; nt < 4; nt++) {
                float e0 = ex2(accS[nt][0] * KLOG2);
                float e1 = ex2(accS[nt][1] * KLOG2);
                float e2 = ex2(accS[nt][2] * KLOG2);
                float e3 = ex2(accS[nt][3] * KLOG2);
                rs0 += e0 + e1; rs1 += e2 + e3;
                int gcol = k0 + colbase + nt * 8 + c * 2;
                *reinterpret_cast<float2*>(&outp[(size_t)grow * Sc + gcol])       = make_float2(e0, e1);
                *reinterpret_cast<float2*>(&outp[(size_t)(grow + 8) * Sc + gcol]) = make_float2(e2, e3);
                accS[nt][0] = e0; accS[nt][1] = e1; accS[nt][2] = e2; accS[nt][3] = e3;
            }

#pragma unroll
            for (int s4 = 0; s4 < 4; s4++) {
                float x0 = __shfl_sync(0xffffffffu, accS[s4][0], src1);
                float x1 = __shfl_sync(0xffffffffu, accS[s4][1], src1);
                float y0 = __shfl_sync(0xffffffffu, accS[s4][2], src1);
                float y1 = __shfl_sync(0xffffffffu, accS[s4][3], src1);
                float z0 = __shfl_sync(0xffffffffu, accS[s4][0], src2);
                float z1 = __shfl_sync(0xffffffffu, accS[s4][1], src2);
                float w0 = __shfl_sync(0xffffffffu, accS[s4][2], src2);
                float w1 = __shfl_sync(0xffffffffu, accS[s4][3], src2);
                uint32_t af[4];
                af[0] = f2tf(odd ? x1 : x0);
                af[1] = f2tf(odd ? y1 : y0);
                af[2] = f2tf(odd ? z1 : z0);
                af[3] = f2tf(odd ? w1 : w0);
                const int vr = colbase + s4 * 8 + c;
#pragma unroll
                for (int nt = 0; nt < 8; nt++) {
                    uint32_t bf[2];
                    bf[0] = __float_as_uint(sV[vr * 68 + nt * 8 + g]);
                    bf[1] = __float_as_uint(sV[(vr + 4) * 68 + nt * 8 + g]);
                    mma8(accU[nt], af, bf);
                }
            }
        }

        if (kt + 1 < 16) cpa_wait0();
        __syncthreads();
    }

    float* red  = smf + FRED;
    float* red2 = smf + FRED2;
    {
        float v0 = rs0, v1 = rs1;
        v0 += __shfl_xor_sync(0xffffffffu, v0, 1);
        v0 += __shfl_xor_sync(0xffffffffu, v0, 2);
        v1 += __shfl_xor_sync(0xffffffffu, v1, 1);
        v1 += __shfl_xor_sync(0xffffffffu, v1, 2);
        if (c == 0) {
            red[(wm * 16 + g) * 2 + wn]     = v0;
            red[(wm * 16 + g + 8) * 2 + wn] = v1;
        }
    }
    __syncthreads();
    if (tid < 128) {
        float iv = 1.0f / (red[tid * 2] + red[tid * 2 + 1]);
        invg[(size_t)bh * Sc + row0 + tid] = iv;
        red2[tid] = iv;
    }
    __syncthreads();

    float* uRed = smf;
    if (wn == 1) {
#pragma unroll
        for (int nt = 0; nt < 8; nt++) {
            int rr = wm * 16 + g, cc = nt * 8 + c * 2;
            uRed[rr * 68 + cc]           = accU[nt][0];
            uRed[rr * 68 + cc + 1]       = accU[nt][1];
            uRed[(rr + 8) * 68 + cc]     = accU[nt][2];
            uRed[(rr + 8) * 68 + cc + 1] = accU[nt][3];
        }
    }
    __syncthreads();
    if (wn == 0) {
        float* cp = ctx + (size_t)(b * Sc + row0) * Dc + h * HDc;
        int rr = wm * 16 + g;
        float iv0 = red2[rr], iv1 = red2[rr + 8];
#pragma unroll
        for (int nt = 0; nt < 8; nt++) {
            int cc = nt * 8 + c * 2;
            float u0 = (accU[nt][0] + uRed[rr * 68 + cc]) * iv0;
            float u1 = (accU[nt][1] + uRed[rr * 68 + cc + 1]) * iv0;
            float u2 = (accU[nt][2] + uRed[(rr + 8) * 68 + cc]) * iv1;
            float u3 = (accU[nt][3] + uRed[(rr + 8) * 68 + cc + 1]) * iv1;
            cp[(size_t)rr * Dc + cc]           = tf32_round(u0);
            cp[(size_t)rr * Dc + cc + 1]       = tf32_round(u1);
            cp[(size_t)(rr + 8) * Dc + cc]     = tf32_round(u2);
            cp[(size_t)(rr + 8) * Dc + cc + 1] = tf32_round(u3);
        }
    }
}

// ============================================================================
// normalize a range of attn in place: attn[row, :] *= inv[row]
// ============================================================================
__global__ void norm_k(float4* __restrict__ attn4, const float* __restrict__ inv,
                       size_t base4, size_t n4) {
    size_t i = (size_t)blockIdx.x * blockDim.x + threadIdx.x;
    const size_t stride = (size_t)gridDim.x * blockDim.x;
    for (; i < n4; i += stride) {
        size_t idx = base4 + i;
        float s = __ldg(&inv[idx >> 9]);   // 512 float4 per row
        float4 v = attn4[idx];
        v.x *= s; v.y *= s; v.z *= s; v.w *= s;
        attn4[idx] = v;
    }
}

// ---------------------------------------------------------------------------
// Side stream + events (host objects created once on the eager first call;
// captured GPU work identical every call).
// ---------------------------------------------------------------------------
static cudaStream_t get_s2() {
    static cudaStream_t s = []{
        cudaStream_t t; cudaStreamCreateWithFlags(&t, cudaStreamNonBlocking); return t;
    }();
    return s;
}
static cudaEvent_t get_ev(int which) {
    static cudaEvent_t ev[5] = { nullptr, nullptr, nullptr, nullptr, nullptr };
    static bool init = []{
        for (int i = 0; i < 5; i++)
            cudaEventCreateWithFlags(&ev[i], cudaEventDisableTiming);
        return true;
    }();
    (void)init;
    return ev[which];
}

extern "C" void kernel_launch(void* const* d_in, const int* in_sizes, int n_in,
                              void* d_out, int out_size) {
    const float* query = (const float*)d_in[0];
    const float* key   = (const float*)d_in[1];
    const float* value = (const float*)d_in[2];
    const float* Wq = (const float*)d_in[3];
    const float* bq = (const float*)d_in[4];
    const float* Wk = (const float*)d_in[5];
    const float* bk = (const float*)d_in[6];
    const float* Wv = (const float*)d_in[7];
    const float* bv = (const float*)d_in[8];
    const float* Wo = (const float*)d_in[9];
    const float* bo = (const float*)d_in[10];

    float* out = (float*)d_out;
    const size_t OUT_E  = (size_t)Bc * Sc * Dc;
    const size_t ATTN_E = (size_t)BHc * Sc * Sc;

    float* attn;
    if ((size_t)out_size >= OUT_E + ATTN_E) {
        attn = out + OUT_E;
    } else {
        void* p = nullptr; cudaGetSymbolAddress(&p, g_attn_fb); attn = (float*)p;
    }
    float* Qp;   { void* p; cudaGetSymbolAddress(&p, g_Q);      Qp = (float*)p; }
    float* Kp;   { void* p; cudaGetSymbolAddress(&p, g_K);      Kp = (float*)p; }
    float* Vp;   { void* p; cudaGetSymbolAddress(&p, g_V);      Vp = (float*)p; }
    float* Cx;   { void* p; cudaGetSymbolAddress(&p, g_ctx);    Cx = (float*)p; }
    float* isum; { void* p; cudaGetSymbolAddress(&p, g_invsum); isum = (float*)p; }
    float* qin;  { void* p; cudaGetSymbolAddress(&p, g_qin);    qin = (float*)p; }
    float* kin;  { void* p; cudaGetSymbolAddress(&p, g_kin);    kin = (float*)p; }
    float* vin;  { void* p; cudaGetSymbolAddress(&p, g_vin);    vin = (float*)p; }
    float* wq;   { void* p; cudaGetSymbolAddress(&p, g_wq);     wq = (float*)p; }
    float* wk;   { void* p; cudaGetSymbolAddress(&p, g_wk);     wk = (float*)p; }
    float* wv;   { void* p; cudaGetSymbolAddress(&p, g_wv);     wv = (float*)p; }
    float* wo;   { void* p; cudaGetSymbolAddress(&p, g_wo);     wo = (float*)p; }

    cudaFuncSetAttribute(fused_attn, cudaFuncAttributeMaxDynamicSharedMemorySize,
                         FTOT * 4);

    cudaStream_t s2 = get_s2();
    cudaEvent_t evQ0 = get_ev(0), evQ1 = get_ev(1);
    cudaEvent_t evA = get_ev(2), evB = get_ev(3), evJoin = get_ev(4);

    const int M = Bc * Sc;                      // 4096
    dim3 thr(256);
    const size_t HALF4 = ATTN_E / 8;            // half of attn in float4 units
    const size_t ROWS_B1 = (size_t)Sc * Dc;     // element offset of batch 1

    prep_round<<<dim3(256, 1, 7), thr>>>(
        (const float4*)query, (const float4*)key, (const float4*)value,
        (const float4*)Wq, (const float4*)Wk, (const float4*)Wv, (const float4*)Wo,
        (float4*)qin, (float4*)kin, (float4*)vin,
        (float4*)wq, (float4*)wk, (float4*)wv, (float4*)wo);

    // ---- qkv batch 0 (full machine) ----
    dim3 gqkv(Dc / 128, Sc / 128, 3);           // (8, 16, 3)
    qkv_gemm<<<gqkv, thr>>>(qin, kin, vin, wq, bq, wk, bk, wv, bv, Qp, Kp, Vp);
    cudaEventRecord(evQ0, 0);

    // s2: qkv batch 1 — overlaps fused_A (batch 0) below
    cudaStreamWaitEvent(s2, evQ0, 0);
    qkv_gemm<<<gqkv, thr, 0, s2>>>(qin + ROWS_B1, kin + ROWS_B1, vin + ROWS_B1,
                                   wq, bq, wk, bk, wv, bv,
                                   Qp + ROWS_B1, Kp + ROWS_B1, Vp + ROWS_B1);
    cudaEventRecord(evQ1, s2);

    // ---- fused attention halves ----
    dim3 gfa(Sc / 128, BHc / 2);                // (16, 16)

    fused_attn<<<gfa, dim3(512), FTOT * 4>>>(Qp, Kp, Vp, attn, isum, Cx, 0);
    cudaEventRecord(evA, 0);

    cudaStreamWaitEvent(0, evQ1, 0);            // batch-1 Q/K/V must be ready
    fused_attn<<<gfa, dim3(512), FTOT * 4>>>(Qp, Kp, Vp, attn, isum, Cx, BHc / 2);
    cudaEventRecord(evB, 0);

    // s2: norm first half while second half of fused runs on s0
    cudaStreamWaitEvent(s2, evA, 0);
    norm_k<<<2368, 256, 0, s2>>>((float4*)attn, isum, 0, HALF4);

    // out-projection on s0 (fat blocks claim SMs first)
    gemm_bias_tc<<<dim3(Dc / 128, M / 128), thr>>>(Cx, wo, bo, out, M, Dc, Dc);

    // s2: norm second half (after fused_B), overlapping out-proj
    cudaStreamWaitEvent(s2, evB, 0);
    norm_k<<<2368, 256, 0, s2>>>((float4*)attn, isum, HALF4, HALF4);

    // join
    cudaEventRecord(evJoin, s2);
    cudaStreamWaitEvent(0, evJoin, 0);
}

// round 16
// speedup vs baseline: 1.0731x; 1.0731x over previous
#include <cuda_runtime.h>
#include <cstdint>

#define Bc 2
#define Sc 2048
#define Dc 1024
#define Hc 16
#define HDc 64
#define BHc (Bc*Hc)
#define SCALEc 0.125f              // 64^-0.5
#define KLOG2 0.1803368801111243f // SCALEc * log2(e)

// ---- scratch (allocation-free rule: __device__ globals) --------------------
__device__ float g_Q[(size_t)Bc * Sc * Dc];
__device__ float g_K[(size_t)Bc * Sc * Dc];
__device__ float g_V[(size_t)Bc * Sc * Dc];
__device__ float g_ctx[(size_t)Bc * Sc * Dc];
__device__ float g_invsum[(size_t)BHc * Sc];
// pre-rounded (tf32) copies of inputs + weights
__device__ float g_qin[(size_t)Bc * Sc * Dc];
__device__ float g_kin[(size_t)Bc * Sc * Dc];
__device__ float g_vin[(size_t)Bc * Sc * Dc];
__device__ float g_wq[(size_t)Dc * Dc];
__device__ float g_wk[(size_t)Dc * Dc];
__device__ float g_wv[(size_t)Dc * Dc];
__device__ float g_wo[(size_t)Dc * Dc];
__device__ float g_attn_fb[(size_t)BHc * Sc * Sc];   // fallback if out only holds `output`

// ---- helpers ----------------------------------------------------------------
__device__ __forceinline__ float tf32_round(float x) {
    return __uint_as_float((__float_as_uint(x) + 0x1000u) & 0xFFFFE000u);
}
__device__ __forceinline__ uint32_t f2tf(float x) {
    uint32_t r; asm("cvt.rna.tf32.f32 %0, %1;" : "=r"(r) : "f"(x)); return r;
}
__device__ __forceinline__ float ex2(float x) {
    float r; asm("ex2.approx.f32 %0, %1;" : "=f"(r) : "f"(x)); return r;
}
__device__ __forceinline__ void mma8(float* d, const uint32_t* a, const uint32_t* b) {
    asm volatile(
        "mma.sync.aligned.m16n8k8.row.col.f32.tf32.tf32.f32 "
        "{%0,%1,%2,%3}, {%4,%5,%6,%7}, {%8,%9}, {%0,%1,%2,%3};\n"
        : "+f"(d[0]), "+f"(d[1]), "+f"(d[2]), "+f"(d[3])
        : "r"(a[0]), "r"(a[1]), "r"(a[2]), "r"(a[3]), "r"(b[0]), "r"(b[1]));
}
__device__ __forceinline__ uint32_t smem_u32(const void* p) {
    uint32_t r;
    asm("{ .reg .u64 t; cvta.to.shared.u64 t, %1; cvt.u32.u64 %0, t; }"
        : "=r"(r) : "l"(p));
    return r;
}
__device__ __forceinline__ void cpa16(uint32_t saddr, const void* g) {
    asm volatile("cp.async.cg.shared.global [%0], [%1], 16;" :: "r"(saddr), "l"(g));
}
__device__ __forceinline__ void cpa_commit() { asm volatile("cp.async.commit_group;"); }
__device__ __forceinline__ void cpa_wait0()  { asm volatile("cp.async.wait_group 0;"); }
__device__ __forceinline__ void cpa_wait1()  { asm volatile("cp.async.wait_group 1;"); }

// ============================================================================
// prep: round inputs + weights to tf32 (producer-side rounding).
// ============================================================================
__global__ __launch_bounds__(256)
void prep_round(const float4* __restrict__ q, const float4* __restrict__ k,
                const float4* __restrict__ v,
                const float4* __restrict__ wq, const float4* __restrict__ wk,
                const float4* __restrict__ wv, const float4* __restrict__ wo,
                float4* __restrict__ oq, float4* __restrict__ ok,
                float4* __restrict__ ov,
                float4* __restrict__ owq, float4* __restrict__ owk,
                float4* __restrict__ owv, float4* __restrict__ owo) {
    const float4* src; float4* dst; size_t n4;
    const size_t NIN = (size_t)Bc * Sc * Dc / 4;
    const size_t NW  = (size_t)Dc * Dc / 4;
    switch (blockIdx.z) {
        case 0: src = q;  dst = oq;  n4 = NIN; break;
        case 1: src = k;  dst = ok;  n4 = NIN; break;
        case 2: src = v;  dst = ov;  n4 = NIN; break;
        case 3: src = wq; dst = owq; n4 = NW;  break;
        case 4: src = wk; dst = owk; n4 = NW;  break;
        case 5: src = wv; dst = owv; n4 = NW;  break;
        default: src = wo; dst = owo; n4 = NW;  break;
    }
    size_t i = (size_t)blockIdx.x * 256 + threadIdx.x;
    const size_t stride = (size_t)gridDim.x * 256;
    for (; i < n4; i += stride) {
        float4 t = src[i];
        t.x = tf32_round(t.x); t.y = tf32_round(t.y);
        t.z = tf32_round(t.z); t.w = tf32_round(t.w);
        dst[i] = t;
    }
}

// ============================================================================
// GEMM + bias: cp.async double-buffered, BK=16, pure-truncation tf32
// fragments (operands pre-rounded, so truncation == rna).
// ============================================================================
struct GemmSmem {
    float As[2][128][20];
    float Bs[2][16][136];
};

template<bool RND_OUT>
__device__ __forceinline__
void gemm_body(const float* __restrict__ A, const float* __restrict__ W,
               const float* __restrict__ bias, float* __restrict__ C,
               int M, int N, int K, GemmSmem& sm) {
    const int tid = threadIdx.x;
    const int lane = tid & 31, warp = tid >> 5;
    const int wm = warp >> 2, wn = warp & 3;
    const int row0 = blockIdx.y * 128, col0 = blockIdx.x * 128;
    const int r_lo = lane >> 2, c_lo = lane & 3;

    const int rowA = tid >> 1, colA = (tid & 1) * 8;
    const int rowB = tid >> 4, colB = (tid & 15) * 8;

    const uint32_t sA[2] = { smem_u32(&sm.As[0][rowA][colA]),
                             smem_u32(&sm.As[1][rowA][colA]) };
    const uint32_t sB[2] = { smem_u32(&sm.Bs[0][rowB][colB]),
                             smem_u32(&sm.Bs[1][rowB][colB]) };
    const float* gA = A + (size_t)(row0 + rowA) * K + colA;
    const float* gB = W + (size_t)rowB * N + col0 + colB;

    float acc[4][4][4] = {};

    cpa16(sA[0], gA); cpa16(sA[0] + 16, gA + 4);
    cpa16(sB[0], gB); cpa16(sB[0] + 16, gB + 4);
    cpa_commit();

    const int nk = K >> 4;
    for (int kt = 0; kt < nk; kt++) {
        const int s = kt & 1;
        if (kt + 1 < nk) {
            const float* gA2 = gA + (kt + 1) * 16;
            const float* gB2 = gB + (size_t)(kt + 1) * 16 * N;
            cpa16(sA[s ^ 1], gA2); cpa16(sA[s ^ 1] + 16, gA2 + 4);
            cpa16(sB[s ^ 1], gB2); cpa16(sB[s ^ 1] + 16, gB2 + 4);
            cpa_commit();
            cpa_wait1();
        } else {
            cpa_wait0();
        }
        __syncthreads();

        const float (*As_)[20]  = sm.As[s];
        const float (*Bs_)[136] = sm.Bs[s];
#pragma unroll
        for (int ks = 0; ks < 16; ks += 8) {
            uint32_t af[4][4], bf[4][2];
#pragma unroll
            for (int mt = 0; mt < 4; mt++) {
                int rb = wm * 64 + mt * 16 + r_lo;
                af[mt][0] = __float_as_uint(As_[rb][ks + c_lo]);
                af[mt][1] = __float_as_uint(As_[rb + 8][ks + c_lo]);
                af[mt][2] = __float_as_uint(As_[rb][ks + 4 + c_lo]);
                af[mt][3] = __float_as_uint(As_[rb + 8][ks + 4 + c_lo]);
            }
#pragma unroll
            for (int nt = 0; nt < 4; nt++) {
                int cb = wn * 32 + nt * 8 + r_lo;
                bf[nt][0] = __float_as_uint(Bs_[ks + c_lo][cb]);
                bf[nt][1] = __float_as_uint(Bs_[ks + 4 + c_lo][cb]);
            }
#pragma unroll
            for (int mt = 0; mt < 4; mt++)
#pragma unroll
                for (int nt = 0; nt < 4; nt++)
                    mma8(acc[mt][nt], af[mt], bf[nt]);
        }
        __syncthreads();
    }

#pragma unroll
    for (int mt = 0; mt < 4; mt++) {
        int row = row0 + wm * 64 + mt * 16 + r_lo;
#pragma unroll
        for (int nt = 0; nt < 4; nt++) {
            int col = col0 + wn * 32 + nt * 8 + c_lo * 2;
            float b0 = bias[col], b1 = bias[col + 1];
            float v0 = acc[mt][nt][0] + b0, v1 = acc[mt][nt][1] + b1;
            float v2 = acc[mt][nt][2] + b0, v3 = acc[mt][nt][3] + b1;
            if (RND_OUT) {
                v0 = tf32_round(v0); v1 = tf32_round(v1);
                v2 = tf32_round(v2); v3 = tf32_round(v3);
            }
            C[(size_t)row * N + col]           = v0;
            C[(size_t)row * N + col + 1]       = v1;
            C[(size_t)(row + 8) * N + col]     = v2;
            C[(size_t)(row + 8) * N + col + 1] = v3;
        }
    }
}

__global__ __launch_bounds__(256)
void gemm_bias_tc(const float* __restrict__ A, const float* __restrict__ W,
                  const float* __restrict__ bias, float* __restrict__ C,
                  int M, int N, int K) {
    __shared__ GemmSmem sm;
    gemm_body<false>(A, W, bias, C, M, N, K, sm);
}

__global__ __launch_bounds__(256)
void qkv_gemm(const float* __restrict__ q, const float* __restrict__ k,
              const float* __restrict__ v,
              const float* __restrict__ Wq, const float* __restrict__ bq,
              const float* __restrict__ Wk, const float* __restrict__ bk,
              const float* __restrict__ Wv, const float* __restrict__ bv,
              float* __restrict__ Qo, float* __restrict__ Ko, float* __restrict__ Vo) {
    __shared__ GemmSmem sm;
    const float *A, *W, *bias; float* C;
    if (blockIdx.z == 0)      { A = q; W = Wq; bias = bq; C = Qo; }
    else if (blockIdx.z == 1) { A = k; W = Wk; bias = bk; C = Ko; }
    else                      { A = v; W = Wv; bias = bv; C = Vo; }
    gemm_body<true>(A, W, bias, C, Bc * Sc, Dc, Dc, sm);
}

// ============================================================================
// Fused attention v5: 256 threads (8 warps, 4m x 2n), 32 q-rows per warp
// (mt=2) -> every K/V B-fragment feeds 2 mma (half the LDS per mma).
// 128 q-rows/block, 128-key K/V tiles double-buffered, stride 68.
// ============================================================================
#define FK0 0
#define FK1 8704
#define FV0 17408
#define FV1 26112
#define FRED 34816
#define FRED2 35072
#define FTOT 35200            // *4 = 140800 bytes

__global__ __launch_bounds__(256)
void fused_attn(const float* __restrict__ Qp, const float* __restrict__ Kp,
                const float* __restrict__ Vp, float* __restrict__ attn,
                float* __restrict__ invg, float* __restrict__ ctx, int bh_base) {
    extern __shared__ float smf[];
    const uint32_t sbase = smem_u32(smf);

    const int bh = bh_base + blockIdx.y, b = bh >> 4, h = bh & 15;
    const int row0 = blockIdx.x * 128;
    const float* Qh = Qp + (size_t)b * Sc * Dc + h * HDc;
    const float* Kh = Kp + (size_t)b * Sc * Dc + h * HDc;
    const float* Vh = Vp + (size_t)b * Sc * Dc + h * HDc;
    float* outp = attn + (size_t)bh * Sc * Sc;

    const int tid = threadIdx.x, lane = tid & 31, warp = tid >> 5;
    const int wm = warp >> 1, wn = warp & 1;   // 4m x 2n, 32 rows per m-warp
    const int g = lane >> 2, c = lane & 3;

    const int ldr0 = tid >> 4;                 // rows 0..15 (+16 per i, 8 iters)
    const int ldc4 = (tid & 15) * 4;

    {
#pragma unroll
        for (int i = 0; i < 8; i++) {
            int r = ldr0 + i * 16;
            cpa16(sbase + (uint32_t)(FK0 + r * 68 + ldc4) * 4, Kh + (size_t)r * Dc + ldc4);
            cpa16(sbase + (uint32_t)(FV0 + r * 68 + ldc4) * 4, Vh + (size_t)r * Dc + ldc4);
        }
        cpa_commit();
    }

    // Q fragments: raw bits (Qp pre-rounded to tf32 by qkv epilogue)
    uint32_t qf[2][8][4];
#pragma unroll
    for (int mt = 0; mt < 2; mt++) {
        const int qr = row0 + wm * 32 + mt * 16;
#pragma unroll
        for (int s8 = 0; s8 < 8; s8++) {
            qf[mt][s8][0] = __float_as_uint(Qh[(size_t)(qr + g)     * Dc + s8 * 8 + c]);
            qf[mt][s8][1] = __float_as_uint(Qh[(size_t)(qr + g + 8) * Dc + s8 * 8 + c]);
            qf[mt][s8][2] = __float_as_uint(Qh[(size_t)(qr + g)     * Dc + s8 * 8 + c + 4]);
            qf[mt][s8][3] = __float_as_uint(Qh[(size_t)(qr + g + 8) * Dc + s8 * 8 + c + 4]);
        }
    }

    cpa_wait0();
    __syncthreads();

    float accU[2][8][4] = {};
    float rs[2][2] = {};

    const int src1 = (lane & ~3) | (c >> 1);
    const int src2 = src1 + 2;
    const bool odd = (c & 1);

    for (int kt = 0; kt < 16; kt++) {
        const int s = kt & 1;
        if (kt + 1 < 16) {
            const float* gk = Kh + (size_t)((kt + 1) * 128) * Dc;
            const float* gv = Vh + (size_t)((kt + 1) * 128) * Dc;
            const int KD = s ? FK0 : FK1;
            const int VD = s ? FV0 : FV1;
#pragma unroll
            for (int i = 0; i < 8; i++) {
                int r = ldr0 + i * 16;
                cpa16(sbase + (uint32_t)(KD + r * 68 + ldc4) * 4, gk + (size_t)r * Dc + ldc4);
                cpa16(sbase + (uint32_t)(VD + r * 68 + ldc4) * 4, gv + (size_t)r * Dc + ldc4);
            }
            cpa_commit();
        }
        const float* sK = smf + (s ? FK1 : FK0);
        const float* sV = smf + (s ? FV1 : FV0);
        const int k0 = kt * 128;

#pragma unroll
        for (int half = 0; half < 2; half++) {
            const int colbase = wn * 64 + half * 32;

            // ---- S = Q K^T: 32 rows x 32 keys, k=64 (bf reused across mt) ----
            float accS[2][4][4] = {};
#pragma unroll
            for (int s8 = 0; s8 < 8; s8++) {
                uint32_t bf[4][2];
#pragma unroll
                for (int nt = 0; nt < 4; nt++) {
                    int kc = colbase + nt * 8 + g;
                    bf[nt][0] = __float_as_uint(sK[kc * 68 + s8 * 8 + c]);
                    bf[nt][1] = __float_as_uint(sK[kc * 68 + s8 * 8 + c + 4]);
                }
#pragma unroll
                for (int nt = 0; nt < 4; nt++) {
                    mma8(accS[0][nt], qf[0][s8], bf[nt]);
                    mma8(accS[1][nt], qf[1][s8], bf[nt]);
                }
            }

            // ---- exp + rowsum + unnormalized E -> gmem ----
#pragma unroll
            for (int mt = 0; mt < 2; mt++) {
                const int grow = row0 + wm * 32 + mt * 16 + g;
#pragma unroll
                for (int nt = 0; nt < 4; nt++) {
                    float e0 = ex2(accS[mt][nt][0] * KLOG2);
                    float e1 = ex2(accS[mt][nt][1] * KLOG2);
                    float e2 = ex2(accS[mt][nt][2] * KLOG2);
                    float e3 = ex2(accS[mt][nt][3] * KLOG2);
                    rs[mt][0] += e0 + e1; rs[mt][1] += e2 + e3;
                    int gcol = k0 + colbase + nt * 8 + c * 2;
                    *reinterpret_cast<float2*>(&outp[(size_t)grow * Sc + gcol])       = make_float2(e0, e1);
                    *reinterpret_cast<float2*>(&outp[(size_t)(grow + 8) * Sc + gcol]) = make_float2(e2, e3);
                    accS[mt][nt][0] = e0; accS[mt][nt][1] = e1;
                    accS[mt][nt][2] = e2; accS[mt][nt][3] = e3;
                }
            }

            // ---- PV: shuffle-transpose E frags; V bf reused across mt ----
#pragma unroll
            for (int s4 = 0; s4 < 4; s4++) {
                uint32_t af[2][4];
#pragma unroll
                for (int mt = 0; mt < 2; mt++) {
                    float x0 = __shfl_sync(0xffffffffu, accS[mt][s4][0], src1);
                    float x1 = __shfl_sync(0xffffffffu, accS[mt][s4][1], src1);
                    float y0 = __shfl_sync(0xffffffffu, accS[mt][s4][2], src1);
                    float y1 = __shfl_sync(0xffffffffu, accS[mt][s4][3], src1);
                    float z0 = __shfl_sync(0xffffffffu, accS[mt][s4][0], src2);
                    float z1 = __shfl_sync(0xffffffffu, accS[mt][s4][1], src2);
                    float w0 = __shfl_sync(0xffffffffu, accS[mt][s4][2], src2);
                    float w1 = __shfl_sync(0xffffffffu, accS[mt][s4][3], src2);
                    af[mt][0] = f2tf(odd ? x1 : x0);
                    af[mt][1] = f2tf(odd ? y1 : y0);
                    af[mt][2] = f2tf(odd ? z1 : z0);
                    af[mt][3] = f2tf(odd ? w1 : w0);
                }
                const int vr = colbase + s4 * 8 + c;
#pragma unroll
                for (int nt = 0; nt < 8; nt++) {
                    uint32_t bf[2];
                    bf[0] = __float_as_uint(sV[vr * 68 + nt * 8 + g]);
                    bf[1] = __float_as_uint(sV[(vr + 4) * 68 + nt * 8 + g]);
                    mma8(accU[0][nt], af[0], bf);
                    mma8(accU[1][nt], af[1], bf);
                }
            }
        }

        if (kt + 1 < 16) cpa_wait0();
        __syncthreads();
    }

    // ---- rowsum reduction -> inv ----
    float* red  = smf + FRED;
    float* red2 = smf + FRED2;
#pragma unroll
    for (int mt = 0; mt < 2; mt++) {
#pragma unroll
        for (int h2 = 0; h2 < 2; h2++) {
            float v = rs[mt][h2];
            v += __shfl_xor_sync(0xffffffffu, v, 1);
            v += __shfl_xor_sync(0xffffffffu, v, 2);
            if (c == 0)
                red[(wm * 32 + mt * 16 + g + h2 * 8) * 2 + wn] = v;
        }
    }
    __syncthreads();
    if (tid < 128) {
        float iv = 1.0f / (red[tid * 2] + red[tid * 2 + 1]);
        invg[(size_t)bh * Sc + row0 + tid] = iv;
        red2[tid] = iv;
    }
    __syncthreads();

    // ---- cross-warp U reduction (wn=1 -> smem, wn=0 adds + writes ctx) ----
    float* uRed = smf;   // reuse K0 region (128x68 floats)
    if (wn == 1) {
#pragma unroll
        for (int mt = 0; mt < 2; mt++) {
            int rr = wm * 32 + mt * 16 + g;
#pragma unroll
            for (int nt = 0; nt < 8; nt++) {
                int cc = nt * 8 + c * 2;
                uRed[rr * 68 + cc]           = accU[mt][nt][0];
                uRed[rr * 68 + cc + 1]       = accU[mt][nt][1];
                uRed[(rr + 8) * 68 + cc]     = accU[mt][nt][2];
                uRed[(rr + 8) * 68 + cc + 1] = accU[mt][nt][3];
            }
        }
    }
    __syncthreads();
    if (wn == 0) {
        float* cp = ctx + (size_t)(b * Sc + row0) * Dc + h * HDc;
#pragma unroll
        for (int mt = 0; mt < 2; mt++) {
            int rr = wm * 32 + mt * 16 + g;
            float iv0 = red2[rr], iv1 = red2[rr + 8];
#pragma unroll
            for (int nt = 0; nt < 8; nt++) {
                int cc = nt * 8 + c * 2;
                float u0 = (accU[mt][nt][0] + uRed[rr * 68 + cc]) * iv0;
                float u1 = (accU[mt][nt][1] + uRed[rr * 68 + cc + 1]) * iv0;
                float u2 = (accU[mt][nt][2] + uRed[(rr + 8) * 68 + cc]) * iv1;
                float u3 = (accU[mt][nt][3] + uRed[(rr + 8) * 68 + cc + 1]) * iv1;
                cp[(size_t)rr * Dc + cc]           = tf32_round(u0);
                cp[(size_t)rr * Dc + cc + 1]       = tf32_round(u1);
                cp[(size_t)(rr + 8) * Dc + cc]     = tf32_round(u2);
                cp[(size_t)(rr + 8) * Dc + cc + 1] = tf32_round(u3);
            }
        }
    }
}

// ============================================================================
// normalize a range of attn in place: attn[row, :] *= inv[row]
// ============================================================================
__global__ void norm_k(float4* __restrict__ attn4, const float* __restrict__ inv,
                       size_t base4, size_t n4) {
    size_t i = (size_t)blockIdx.x * blockDim.x + threadIdx.x;
    const size_t stride = (size_t)gridDim.x * blockDim.x;
    for (; i < n4; i += stride) {
        size_t idx = base4 + i;
        float s = __ldg(&inv[idx >> 9]);   // 512 float4 per row
        float4 v = attn4[idx];
        v.x *= s; v.y *= s; v.z *= s; v.w *= s;
        attn4[idx] = v;
    }
}

// ---------------------------------------------------------------------------
// Side stream + events (host objects created once on the eager first call;
// captured GPU work identical every call).
// ---------------------------------------------------------------------------
static cudaStream_t get_s2() {
    static cudaStream_t s = []{
        cudaStream_t t; cudaStreamCreateWithFlags(&t, cudaStreamNonBlocking); return t;
    }();
    return s;
}
static cudaEvent_t get_ev(int which) {
    static cudaEvent_t ev[3] = { nullptr, nullptr, nullptr };
    static bool init = []{
        for (int i = 0; i < 3; i++)
            cudaEventCreateWithFlags(&ev[i], cudaEventDisableTiming);
        return true;
    }();
    (void)init;
    return ev[which];
}

extern "C" void kernel_launch(void* const* d_in, const int* in_sizes, int n_in,
                              void* d_out, int out_size) {
    const float* query = (const float*)d_in[0];
    const float* key   = (const float*)d_in[1];
    const float* value = (const float*)d_in[2];
    const float* Wq = (const float*)d_in[3];
    const float* bq = (const float*)d_in[4];
    const float* Wk = (const float*)d_in[5];
    const float* bk = (const float*)d_in[6];
    const float* Wv = (const float*)d_in[7];
    const float* bv = (const float*)d_in[8];
    const float* Wo = (const float*)d_in[9];
    const float* bo = (const float*)d_in[10];

    float* out = (float*)d_out;
    const size_t OUT_E  = (size_t)Bc * Sc * Dc;
    const size_t ATTN_E = (size_t)BHc * Sc * Sc;

    float* attn;
    if ((size_t)out_size >= OUT_E + ATTN_E) {
        attn = out + OUT_E;
    } else {
        void* p = nullptr; cudaGetSymbolAddress(&p, g_attn_fb); attn = (float*)p;
    }
    float* Qp;   { void* p; cudaGetSymbolAddress(&p, g_Q);      Qp = (float*)p; }
    float* Kp;   { void* p; cudaGetSymbolAddress(&p, g_K);      Kp = (float*)p; }
    float* Vp;   { void* p; cudaGetSymbolAddress(&p, g_V);      Vp = (float*)p; }
    float* Cx;   { void* p; cudaGetSymbolAddress(&p, g_ctx);    Cx = (float*)p; }
    float* isum; { void* p; cudaGetSymbolAddress(&p, g_invsum); isum = (float*)p; }
    float* qin;  { void* p; cudaGetSymbolAddress(&p, g_qin);    qin = (float*)p; }
    float* kin;  { void* p; cudaGetSymbolAddress(&p, g_kin);    kin = (float*)p; }
    float* vin;  { void* p; cudaGetSymbolAddress(&p, g_vin);    vin = (float*)p; }
    float* wq;   { void* p; cudaGetSymbolAddress(&p, g_wq);     wq = (float*)p; }
    float* wk;   { void* p; cudaGetSymbolAddress(&p, g_wk);     wk = (float*)p; }
    float* wv;   { void* p; cudaGetSymbolAddress(&p, g_wv);     wv = (float*)p; }
    float* wo;   { void* p; cudaGetSymbolAddress(&p, g_wo);     wo = (float*)p; }

    cudaFuncSetAttribute(fused_attn, cudaFuncAttributeMaxDynamicSharedMemorySize,
                         FTOT * 4);

    cudaStream_t s2 = get_s2();
    cudaEvent_t evA = get_ev(0), evB = get_ev(1), evJoin = get_ev(2);

    const int M = Bc * Sc;                      // 4096
    dim3 thr(256);
    const size_t HALF4 = ATTN_E / 8;            // half of attn in float4 units

    prep_round<<<dim3(256, 1, 7), thr>>>(
        (const float4*)query, (const float4*)key, (const float4*)value,
        (const float4*)Wq, (const float4*)Wk, (const float4*)Wv, (const float4*)Wo,
        (float4*)qin, (float4*)kin, (float4*)vin,
        (float4*)wq, (float4*)wk, (float4*)wv, (float4*)wo);

    qkv_gemm<<<dim3(Dc / 128, M / 128, 3), thr>>>(qin, kin, vin,
                                                  wq, bq, wk, bk, wv, bv,
                                                  Qp, Kp, Vp);

    // ---- fused attention split into two half-grids (bh 0..15, 16..31) ----
    dim3 gfa(Sc / 128, BHc / 2);                // (16, 16)

    fused_attn<<<gfa, thr, FTOT * 4>>>(Qp, Kp, Vp, attn, isum, Cx, 0);
    cudaEventRecord(evA, 0);

    fused_attn<<<gfa, thr, FTOT * 4>>>(Qp, Kp, Vp, attn, isum, Cx, BHc / 2);
    cudaEventRecord(evB, 0);

    // s2: norm first half while second half of fused runs on s0
    cudaStreamWaitEvent(s2, evA, 0);
    norm_k<<<2368, 256, 0, s2>>>((float4*)attn, isum, 0, HALF4);

    // out-projection on s0 (fat blocks claim SMs first)
    gemm_bias_tc<<<dim3(Dc / 128, M / 128), thr>>>(Cx, wo, bo, out, M, Dc, Dc);

    // s2: norm second half (after fused_B), overlapping out-proj
    cudaStreamWaitEvent(s2, evB, 0);
    norm_k<<<2368, 256, 0, s2>>>((float4*)attn, isum, HALF4, HALF4);

    // join
    cudaEventRecord(evJoin, s2);
    cudaStreamWaitEvent(0, evJoin, 0);
}

// round 17
// speedup vs baseline: 1.5056x; 1.4031x over previous
#include <cuda_runtime.h>
#include <cuda_fp16.h>
#include <cstdint>

#define Bc 2
#define Sc 2048
#define Dc 1024
#define Hc 16
#define HDc 64
#define BHc (Bc*Hc)
#define KLOG2 0.1803368801111243f  // 0.125 * log2(e)
#define ESCALE 0.0625f             // E pre-scale for fp16 headroom
#define BSD ((size_t)Bc * Sc * Dc)

// ---- scratch (allocation-free rule: __device__ globals) --------------------
__device__ __half g_Q16[BSD];
__device__ __half g_K16[BSD];
__device__ __half g_V16[BSD];
__device__ __half g_Vt[(size_t)BHc * HDc * Sc];   // [bh][d][s]
__device__ __half g_ctx16[BSD];
__device__ float  g_invsum[(size_t)BHc * Sc];
__device__ __half g_qin16[BSD];
__device__ __half g_kin16[BSD];
__device__ __half g_vin16[BSD];
__device__ __half g_wq16[(size_t)Dc * Dc];        // k-pair interleaved
__device__ __half g_wk16[(size_t)Dc * Dc];
__device__ __half g_wv16[(size_t)Dc * Dc];
__device__ __half g_wo16[(size_t)Dc * Dc];
__device__ float  g_attn_fb[(size_t)BHc * Sc * Sc];

// ---- helpers ----------------------------------------------------------------
__device__ __forceinline__ float ex2(float x) {
    float r; asm("ex2.approx.f32 %0, %1;" : "=f"(r) : "f"(x)); return r;
}
__device__ __forceinline__ void mma16(float* d, const uint32_t* a, const uint32_t* b) {
    asm volatile(
        "mma.sync.aligned.m16n8k16.row.col.f32.f16.f16.f32 "
        "{%0,%1,%2,%3}, {%4,%5,%6,%7}, {%8,%9}, {%0,%1,%2,%3};\n"
        : "+f"(d[0]), "+f"(d[1]), "+f"(d[2]), "+f"(d[3])
        : "r"(a[0]), "r"(a[1]), "r"(a[2]), "r"(a[3]), "r"(b[0]), "r"(b[1]));
}
__device__ __forceinline__ uint32_t f22h(float lo, float hi) {
    __half2 h = __floats2half2_rn(lo, hi);
    return *reinterpret_cast<uint32_t*>(&h);
}
__device__ __forceinline__ uint32_t smem_u32(const void* p) {
    uint32_t r;
    asm("{ .reg .u64 t; cvta.to.shared.u64 t, %1; cvt.u32.u64 %0, t; }"
        : "=r"(r) : "l"(p));
    return r;
}
__device__ __forceinline__ void cpa16(uint32_t saddr, const void* g) {
    asm volatile("cp.async.cg.shared.global [%0], [%1], 16;" :: "r"(saddr), "l"(g));
}
__device__ __forceinline__ void cpa_commit() { asm volatile("cp.async.commit_group;"); }
__device__ __forceinline__ void cpa_wait0()  { asm volatile("cp.async.wait_group 0;"); }
__device__ __forceinline__ void cpa_wait1()  { asm volatile("cp.async.wait_group 1;"); }

// ============================================================================
// prep: inputs -> fp16 row-major; weights -> fp16 k-pair interleaved:
// Wp[(k>>1)*2N + 2n + (k&1)]
// ============================================================================
__global__ __launch_bounds__(256)
void prep_h(const float4* __restrict__ q, const float4* __restrict__ k,
            const float4* __restrict__ v,
            const float4* __restrict__ wq, const float4* __restrict__ wk,
            const float4* __restrict__ wv, const float4* __restrict__ wo,
            __half* __restrict__ oq, __half* __restrict__ ok,
            __half* __restrict__ ov,
            __half* __restrict__ owq, __half* __restrict__ owk,
            __half* __restrict__ owv, __half* __restrict__ owo) {
    const float4* src; __half* dst; size_t n4; bool wmode;
    const size_t NIN = BSD / 4;
    const size_t NW  = (size_t)Dc * Dc / 4;
    switch (blockIdx.z) {
        case 0: src = q;  dst = oq;  n4 = NIN; wmode = false; break;
        case 1: src = k;  dst = ok;  n4 = NIN; wmode = false; break;
        case 2: src = v;  dst = ov;  n4 = NIN; wmode = false; break;
        case 3: src = wq; dst = owq; n4 = NW;  wmode = true;  break;
        case 4: src = wk; dst = owk; n4 = NW;  wmode = true;  break;
        case 5: src = wv; dst = owv; n4 = NW;  wmode = true;  break;
        default: src = wo; dst = owo; n4 = NW; wmode = true;  break;
    }
    size_t i = (size_t)blockIdx.x * 256 + threadIdx.x;
    const size_t stride = (size_t)gridDim.x * 256;
    for (; i < n4; i += stride) {
        float4 t = src[i];
        if (!wmode) {
            uint32_t u01 = f22h(t.x, t.y), u23 = f22h(t.z, t.w);
            *reinterpret_cast<uint2*>(&dst[i * 4]) = make_uint2(u01, u23);
        } else {
            size_t f = i * 4;
            int kk = (int)(f >> 10), n0 = (int)(f & 1023);
            size_t base = (size_t)(kk >> 1) * 2048 + (kk & 1);
            dst[base + 2 * (n0 + 0)] = __float2half_rn(t.x);
            dst[base + 2 * (n0 + 1)] = __float2half_rn(t.y);
            dst[base + 2 * (n0 + 2)] = __float2half_rn(t.z);
            dst[base + 2 * (n0 + 3)] = __float2half_rn(t.w);
        }
    }
}

// ============================================================================
// V transpose: V16[b*2048+s][h*64+d] -> Vt[bh][d][s].  grid (32,1,32), 256 thr.
// ============================================================================
__global__ __launch_bounds__(256)
void v_transpose(const __half* __restrict__ V16, __half* __restrict__ Vt) {
    __shared__ __half tile[64][72];
    const int bh = blockIdx.z, b = bh >> 4, h = bh & 15;
    const int s0 = blockIdx.x * 64;
    const int tid = threadIdx.x;
#pragma unroll
    for (int p = 0; p < 4; p++) {
        int idx = tid + p * 256;
        int i = idx >> 4, j = (idx & 15) * 4;     // s row i, d col j
        uint2 vv = *reinterpret_cast<const uint2*>(
            &V16[(size_t)(b * Sc + s0 + i) * Dc + h * HDc + j]);
        *reinterpret_cast<uint2*>(&tile[i][j]) = vv;
    }
    __syncthreads();
#pragma unroll
    for (int p = 0; p < 4; p++) {
        int idx = tid + p * 256;
        int d = idx >> 4, sj = (idx & 15) * 4;
        __half h4[4];
        h4[0] = tile[sj + 0][d]; h4[1] = tile[sj + 1][d];
        h4[2] = tile[sj + 2][d]; h4[3] = tile[sj + 3][d];
        *reinterpret_cast<uint2*>(
            &Vt[(size_t)bh * HDc * Sc + (size_t)d * Sc + s0 + sj]) =
            *reinterpret_cast<uint2*>(h4);
    }
}

// ============================================================================
// fp16 GEMM + bias: C[M,N] = A[M,K] @ W[K,N] + b.  BM=BN=128, BK=32,
// 256 thr = 8 warps (2m x 4n), warp 64x32, m16n8k16. A fp16 row-major,
// W fp16 k-pair interleaved. Output half (rn) or float.
// ============================================================================
template<bool HALF_OUT>
__device__ __forceinline__
void gemm_h_body(const __half* __restrict__ A, const __half* __restrict__ Wp,
                 const float* __restrict__ bias, void* __restrict__ Cv,
                 int M, int N, int K) {
    __shared__ __half hA[2][128][40];
    __shared__ __half hB[2][16][272];
    const int tid = threadIdx.x;
    const int lane = tid & 31, warp = tid >> 5;
    const int wm = warp >> 2, wn = warp & 3;
    const int row0 = blockIdx.y * 128, col0 = blockIdx.x * 128;
    const int g = lane >> 2, c = lane & 3;

    // staging coords: A 128x32 halves (512 chunks), B 16 kp x 256 halves (512)
    const int idA0 = tid * 2, idA1 = tid * 2 + 1;
    const int rA0 = idA0 >> 2, cA0 = (idA0 & 3) * 8;
    const int rA1 = idA1 >> 2, cA1 = (idA1 & 3) * 8;
    const int kp0 = idA0 >> 5, ch0 = (idA0 & 31) * 8;
    const int kp1 = idA1 >> 5, ch1 = (idA1 & 31) * 8;

    const uint32_t sA[2] = { smem_u32(&hA[0][0][0]), smem_u32(&hA[1][0][0]) };
    const uint32_t sB[2] = { smem_u32(&hB[0][0][0]), smem_u32(&hB[1][0][0]) };

    float acc[4][4][4] = {};

    // prologue stage 0
    {
        cpa16(sA[0] + (uint32_t)(rA0 * 40 + cA0) * 2, A + (size_t)(row0 + rA0) * K + cA0);
        cpa16(sA[0] + (uint32_t)(rA1 * 40 + cA1) * 2, A + (size_t)(row0 + rA1) * K + cA1);
        cpa16(sB[0] + (uint32_t)(kp0 * 272 + ch0) * 2, Wp + (size_t)kp0 * 2048 + col0 * 2 + ch0);
        cpa16(sB[0] + (uint32_t)(kp1 * 272 + ch1) * 2, Wp + (size_t)kp1 * 2048 + col0 * 2 + ch1);
        cpa_commit();
    }

    const int nk = K >> 5;   // BK=32
    for (int kt = 0; kt < nk; kt++) {
        const int s = kt & 1;
        if (kt + 1 < nk) {
            const int d = s ^ 1;
            const size_t ka = (size_t)(kt + 1) * 32;
            const size_t kb = (size_t)((kt + 1) * 16) * 2048;
            cpa16(sA[d] + (uint32_t)(rA0 * 40 + cA0) * 2, A + (size_t)(row0 + rA0) * K + ka + cA0);
            cpa16(sA[d] + (uint32_t)(rA1 * 40 + cA1) * 2, A + (size_t)(row0 + rA1) * K + ka + cA1);
            cpa16(sB[d] + (uint32_t)(kp0 * 272 + ch0) * 2, Wp + kb + (size_t)kp0 * 2048 + col0 * 2 + ch0);
            cpa16(sB[d] + (uint32_t)(kp1 * 272 + ch1) * 2, Wp + kb + (size_t)kp1 * 2048 + col0 * 2 + ch1);
            cpa_commit();
            cpa_wait1();
        } else {
            cpa_wait0();
        }
        __syncthreads();

        const uint32_t* A32 = reinterpret_cast<const uint32_t*>(&hA[s][0][0]);
        const uint32_t* B32 = reinterpret_cast<const uint32_t*>(&hB[s][0][0]);
#pragma unroll
        for (int j = 0; j < 2; j++) {          // two k16 steps
            uint32_t af[4][4], bf[4][2];
#pragma unroll
            for (int mt = 0; mt < 4; mt++) {
                int rb = wm * 64 + mt * 16 + g;
                af[mt][0] = A32[rb * 20 + j * 8 + c];
                af[mt][1] = A32[(rb + 8) * 20 + j * 8 + c];
                af[mt][2] = A32[rb * 20 + j * 8 + c + 4];
                af[mt][3] = A32[(rb + 8) * 20 + j * 8 + c + 4];
            }
#pragma unroll
            for (int nt = 0; nt < 4; nt++) {
                int nn = wn * 32 + nt * 8 + g;
                bf[nt][0] = B32[(j * 8 + c) * 136 + nn];
                bf[nt][1] = B32[(j * 8 + c + 4) * 136 + nn];
            }
#pragma unroll
            for (int mt = 0; mt < 4; mt++)
#pragma unroll
                for (int nt = 0; nt < 4; nt++)
                    mma16(acc[mt][nt], af[mt], bf[nt]);
        }
        __syncthreads();
    }

#pragma unroll
    for (int mt = 0; mt < 4; mt++) {
        int row = row0 + wm * 64 + mt * 16 + g;
#pragma unroll
        for (int nt = 0; nt < 4; nt++) {
            int col = col0 + wn * 32 + nt * 8 + c * 2;
            float b0 = bias[col], b1 = bias[col + 1];
            float v0 = acc[mt][nt][0] + b0, v1 = acc[mt][nt][1] + b1;
            float v2 = acc[mt][nt][2] + b0, v3 = acc[mt][nt][3] + b1;
            if (HALF_OUT) {
                __half* C = (__half*)Cv;
                C[(size_t)row * N + col]           = __float2half_rn(v0);
                C[(size_t)row * N + col + 1]       = __float2half_rn(v1);
                C[(size_t)(row + 8) * N + col]     = __float2half_rn(v2);
                C[(size_t)(row + 8) * N + col + 1] = __float2half_rn(v3);
            } else {
                float* C = (float*)Cv;
                C[(size_t)row * N + col]           = v0;
                C[(size_t)row * N + col + 1]       = v1;
                C[(size_t)(row + 8) * N + col]     = v2;
                C[(size_t)(row + 8) * N + col + 1] = v3;
            }
        }
    }
}

__global__ __launch_bounds__(256)
void qkv_gemm_h(const __half* __restrict__ q, const __half* __restrict__ k,
                const __half* __restrict__ v,
                const __half* __restrict__ Wq, const float* __restrict__ bq,
                const __half* __restrict__ Wk, const float* __restrict__ bk,
                const __half* __restrict__ Wv, const float* __restrict__ bv,
                __half* __restrict__ Qo, __half* __restrict__ Ko,
                __half* __restrict__ Vo) {
    const __half *A, *W; const float* bias; __half* C;
    if (blockIdx.z == 0)      { A = q; W = Wq; bias = bq; C = Qo; }
    else if (blockIdx.z == 1) { A = k; W = Wk; bias = bk; C = Ko; }
    else                      { A = v; W = Wv; bias = bv; C = Vo; }
    gemm_h_body<true>(A, W, bias, C, Bc * Sc, Dc, Dc);
}

__global__ __launch_bounds__(256)
void outproj_h(const __half* __restrict__ A, const __half* __restrict__ Wp,
               const float* __restrict__ bias, float* __restrict__ C) {
    gemm_h_body<false>(A, Wp, bias, C, Bc * Sc, Dc, Dc);
}

// ============================================================================
// Fused attention fp16: 256 thr (8 warps, 4m x 2n), mt=2 (32 rows/warp),
// 128 q-rows/block, 128-key tiles double-buffered. m16n8k16; PV A-frags
// packed directly from exp'd S accumulators (no shuffle transpose).
// smem halves: K0 0, K1 9216, V0 18432, V1 27136 (V tile [64][136]).
// ============================================================================
#define HK0 0
#define HK1 9216
#define HV0 18432
#define HV1 27136
#define HEND 35840
#define FTOT_BYTES (HEND * 2 + 384 * 4)    // 73216

__global__ __launch_bounds__(256)
void fused_attn_h(const __half* __restrict__ Qp, const __half* __restrict__ Kp,
                  const __half* __restrict__ Vtg, float* __restrict__ attn,
                  float* __restrict__ invg, __half* __restrict__ ctx, int bh_base) {
    extern __shared__ __half smh[];
    const uint32_t sbase = smem_u32(smh);
    float* red  = reinterpret_cast<float*>(smh + HEND);        // 256
    float* red2 = reinterpret_cast<float*>(smh + HEND) + 256;  // 128

    const int bh = bh_base + blockIdx.y, b = bh >> 4, h = bh & 15;
    const int row0 = blockIdx.x * 128;
    const __half* Qh = Qp + (size_t)b * Sc * Dc + h * HDc;
    const __half* Kh = Kp + (size_t)b * Sc * Dc + h * HDc;
    const __half* Vh = Vtg + (size_t)bh * HDc * Sc;
    float* outp = attn + (size_t)bh * Sc * Sc;

    const int tid = threadIdx.x, lane = tid & 31, warp = tid >> 5;
    const int wm = warp >> 1, wn = warp & 1;   // 4m x 2n
    const int g = lane >> 2, c = lane & 3;

    // staging: K 1024 chunks (r=id>>3, ch=id&7), V 1024 chunks (d=id>>4, ch=id&15)
    const int kr = tid >> 3, kc8 = (tid & 7) * 8;
    const int vd = tid >> 4, vc8 = (tid & 15) * 8;

    {
#pragma unroll
        for (int i = 0; i < 4; i++) {
            int r = kr + i * 32;
            cpa16(sbase + (uint32_t)(HK0 + r * 72 + kc8) * 2, Kh + (size_t)r * Dc + kc8);
            int d = vd + i * 16;
            cpa16(sbase + (uint32_t)(HV0 + d * 136 + vc8) * 2, Vh + (size_t)d * Sc + vc8);
        }
        cpa_commit();
    }

    // Q fragments (fp16, exact): [mt][k16 step j][4 regs]
    uint32_t qf[2][4][4];
#pragma unroll
    for (int mt = 0; mt < 2; mt++) {
        const int qr = row0 + wm * 32 + mt * 16;
#pragma unroll
        for (int j = 0; j < 4; j++) {
            qf[mt][j][0] = *reinterpret_cast<const uint32_t*>(&Qh[(size_t)(qr + g)     * Dc + j * 16 + 2 * c]);
            qf[mt][j][1] = *reinterpret_cast<const uint32_t*>(&Qh[(size_t)(qr + g + 8) * Dc + j * 16 + 2 * c]);
            qf[mt][j][2] = *reinterpret_cast<const uint32_t*>(&Qh[(size_t)(qr + g)     * Dc + j * 16 + 2 * c + 8]);
            qf[mt][j][3] = *reinterpret_cast<const uint32_t*>(&Qh[(size_t)(qr + g + 8) * Dc + j * 16 + 2 * c + 8]);
        }
    }

    cpa_wait0();
    __syncthreads();

    float accU[2][8][4] = {};
    float rs[2][2] = {};

    for (int kt = 0; kt < 16; kt++) {
        const int s = kt & 1;
        if (kt + 1 < 16) {
            const __half* gk = Kh + (size_t)((kt + 1) * 128) * Dc;
            const __half* gv = Vh + (kt + 1) * 128;
            const int KD = s ? HK0 : HK1;
            const int VD = s ? HV0 : HV1;
#pragma unroll
            for (int i = 0; i < 4; i++) {
                int r = kr + i * 32;
                cpa16(sbase + (uint32_t)(KD + r * 72 + kc8) * 2, gk + (size_t)r * Dc + kc8);
                int d = vd + i * 16;
                cpa16(sbase + (uint32_t)(VD + d * 136 + vc8) * 2, gv + (size_t)d * Sc + vc8);
            }
            cpa_commit();
        }
        const uint32_t* sK32 = reinterpret_cast<const uint32_t*>(smh + (s ? HK1 : HK0));
        const uint32_t* sV32 = reinterpret_cast<const uint32_t*>(smh + (s ? HV1 : HV0));
        const int k0 = kt * 128;

#pragma unroll
        for (int half = 0; half < 2; half++) {
            const int colbase = wn * 64 + half * 32;

            // ---- S = Q K^T: 32 rows x 32 keys, k=64 (4 k16 steps) ----
            float accS[2][4][4] = {};
#pragma unroll
            for (int j = 0; j < 4; j++) {
                uint32_t bf[4][2];
#pragma unroll
                for (int nt = 0; nt < 4; nt++) {
                    int key = colbase + nt * 8 + g;
                    bf[nt][0] = sK32[key * 36 + j * 8 + c];
                    bf[nt][1] = sK32[key * 36 + j * 8 + c + 4];
                }
#pragma unroll
                for (int nt = 0; nt < 4; nt++) {
                    mma16(accS[0][nt], qf[0][j], bf[nt]);
                    mma16(accS[1][nt], qf[1][j], bf[nt]);
                }
            }

            // ---- exp + rowsum + unnormalized E -> gmem; keep E*ESCALE ----
#pragma unroll
            for (int mt = 0; mt < 2; mt++) {
                const int grow = row0 + wm * 32 + mt * 16 + g;
#pragma unroll
                for (int nt = 0; nt < 4; nt++) {
                    float e0 = ex2(accS[mt][nt][0] * KLOG2);
                    float e1 = ex2(accS[mt][nt][1] * KLOG2);
                    float e2 = ex2(accS[mt][nt][2] * KLOG2);
                    float e3 = ex2(accS[mt][nt][3] * KLOG2);
                    rs[mt][0] += e0 + e1; rs[mt][1] += e2 + e3;
                    int gcol = k0 + colbase + nt * 8 + c * 2;
                    *reinterpret_cast<float2*>(&outp[(size_t)grow * Sc + gcol])       = make_float2(e0, e1);
                    *reinterpret_cast<float2*>(&outp[(size_t)(grow + 8) * Sc + gcol]) = make_float2(e2, e3);
                    accS[mt][nt][0] = e0 * ESCALE; accS[mt][nt][1] = e1 * ESCALE;
                    accS[mt][nt][2] = e2 * ESCALE; accS[mt][nt][3] = e3 * ESCALE;
                }
            }

            // ---- PV: A-frags packed from accS (no shuffle); 2 k16 steps ----
#pragma unroll
            for (int t = 0; t < 2; t++) {
                uint32_t af[2][4];
#pragma unroll
                for (int mt = 0; mt < 2; mt++) {
                    af[mt][0] = f22h(accS[mt][2 * t][0],     accS[mt][2 * t][1]);
                    af[mt][1] = f22h(accS[mt][2 * t][2],     accS[mt][2 * t][3]);
                    af[mt][2] = f22h(accS[mt][2 * t + 1][0], accS[mt][2 * t + 1][1]);
                    af[mt][3] = f22h(accS[mt][2 * t + 1][2], accS[mt][2 * t + 1][3]);
                }
                const int kbase32 = (colbase >> 1) + t * 8;   // u32 offset within key row
#pragma unroll
                for (int nt = 0; nt < 8; nt++) {
                    int dim = nt * 8 + g;
                    uint32_t bf[2];
                    bf[0] = sV32[dim * 68 + kbase32 + c];
                    bf[1] = sV32[dim * 68 + kbase32 + c + 4];
                    mma16(accU[0][nt], af[0], bf);
                    mma16(accU[1][nt], af[1], bf);
                }
            }
        }

        if (kt + 1 < 16) cpa_wait0();
        __syncthreads();
    }

    // ---- rowsum reduction -> inv ----
#pragma unroll
    for (int mt = 0; mt < 2; mt++) {
#pragma unroll
        for (int h2 = 0; h2 < 2; h2++) {
            float v = rs[mt][h2];
            v += __shfl_xor_sync(0xffffffffu, v, 1);
            v += __shfl_xor_sync(0xffffffffu, v, 2);
            if (c == 0)
                red[(wm * 32 + mt * 16 + g + h2 * 8) * 2 + wn] = v;
        }
    }
    __syncthreads();
    if (tid < 128) {
        float iv = 1.0f / (red[tid * 2] + red[tid * 2 + 1]);
        invg[(size_t)bh * Sc + row0 + tid] = iv;
        red2[tid] = iv;
    }
    __syncthreads();

    // ---- cross-warp U reduction (wn=1 -> smem, wn=0 adds + writes ctx) ----
    float* uRed = reinterpret_cast<float*>(smh);   // reuse K region
    if (wn == 1) {
#pragma unroll
        for (int mt = 0; mt < 2; mt++) {
            int rr = wm * 32 + mt * 16 + g;
#pragma unroll
            for (int nt = 0; nt < 8; nt++) {
                int cc = nt * 8 + c * 2;
                uRed[rr * 68 + cc]           = accU[mt][nt][0];
                uRed[rr * 68 + cc + 1]       = accU[mt][nt][1];
                uRed[(rr + 8) * 68 + cc]     = accU[mt][nt][2];
                uRed[(rr + 8) * 68 + cc + 1] = accU[mt][nt][3];
            }
        }
    }
    __syncthreads();
    if (wn == 0) {
        __half* cp = ctx + (size_t)(b * Sc + row0) * Dc + h * HDc;
#pragma unroll
        for (int mt = 0; mt < 2; mt++) {
            int rr = wm * 32 + mt * 16 + g;
            float iv0 = red2[rr] * 16.0f, iv1 = red2[rr + 8] * 16.0f;  // undo ESCALE
#pragma unroll
            for (int nt = 0; nt < 8; nt++) {
                int cc = nt * 8 + c * 2;
                float u0 = (accU[mt][nt][0] + uRed[rr * 68 + cc]) * iv0;
                float u1 = (accU[mt][nt][1] + uRed[rr * 68 + cc + 1]) * iv0;
                float u2 = (accU[mt][nt][2] + uRed[(rr + 8) * 68 + cc]) * iv1;
                float u3 = (accU[mt][nt][3] + uRed[(rr + 8) * 68 + cc + 1]) * iv1;
                cp[(size_t)rr * Dc + cc]           = __float2half_rn(u0);
                cp[(size_t)rr * Dc + cc + 1]       = __float2half_rn(u1);
                cp[(size_t)(rr + 8) * Dc + cc]     = __float2half_rn(u2);
                cp[(size_t)(rr + 8) * Dc + cc + 1] = __float2half_rn(u3);
            }
        }
    }
}

// ============================================================================
// normalize a range of attn in place: attn[row, :] *= inv[row]
// ============================================================================
__global__ void norm_k(float4* __restrict__ attn4, const float* __restrict__ inv,
                       size_t base4, size_t n4) {
    size_t i = (size_t)blockIdx.x * blockDim.x + threadIdx.x;
    const size_t stride = (size_t)gridDim.x * blockDim.x;
    for (; i < n4; i += stride) {
        size_t idx = base4 + i;
        float s = __ldg(&inv[idx >> 9]);
        float4 v = attn4[idx];
        v.x *= s; v.y *= s; v.z *= s; v.w *= s;
        attn4[idx] = v;
    }
}

// ---------------------------------------------------------------------------
static cudaStream_t get_s2() {
    static cudaStream_t s = []{
        cudaStream_t t; cudaStreamCreateWithFlags(&t, cudaStreamNonBlocking); return t;
    }();
    return s;
}
static cudaEvent_t get_ev(int which) {
    static cudaEvent_t ev[3] = { nullptr, nullptr, nullptr };
    static bool init = []{
        for (int i = 0; i < 3; i++)
            cudaEventCreateWithFlags(&ev[i], cudaEventDisableTiming);
        return true;
    }();
    (void)init;
    return ev[which];
}

extern "C" void kernel_launch(void* const* d_in, const int* in_sizes, int n_in,
                              void* d_out, int out_size) {
    const float* query = (const float*)d_in[0];
    const float* key   = (const float*)d_in[1];
    const float* value = (const float*)d_in[2];
    const float* Wq = (const float*)d_in[3];
    const float* bq = (const float*)d_in[4];
    const float* Wk = (const float*)d_in[5];
    const float* bk = (const float*)d_in[6];
    const float* Wv = (const float*)d_in[7];
    const float* bv = (const float*)d_in[8];
    const float* Wo = (const float*)d_in[9];
    const float* bo = (const float*)d_in[10];

    float* out = (float*)d_out;
    const size_t OUT_E  = BSD;
    const size_t ATTN_E = (size_t)BHc * Sc * Sc;

    float* attn;
    if ((size_t)out_size >= OUT_E + ATTN_E) {
        attn = out + OUT_E;
    } else {
        void* p = nullptr; cudaGetSymbolAddress(&p, g_attn_fb); attn = (float*)p;
    }
    __half *Q16, *K16, *V16, *Vt, *ctx16, *q16, *k16, *v16, *wq16, *wk16, *wv16, *wo16;
    float* isum;
    { void* p; cudaGetSymbolAddress(&p, g_Q16);   Q16 = (__half*)p; }
    { void* p; cudaGetSymbolAddress(&p, g_K16);   K16 = (__half*)p; }
    { void* p; cudaGetSymbolAddress(&p, g_V16);   V16 = (__half*)p; }
    { void* p; cudaGetSymbolAddress(&p, g_Vt);    Vt = (__half*)p; }
    { void* p; cudaGetSymbolAddress(&p, g_ctx16); ctx16 = (__half*)p; }
    { void* p; cudaGetSymbolAddress(&p, g_invsum); isum = (float*)p; }
    { void* p; cudaGetSymbolAddress(&p, g_qin16); q16 = (__half*)p; }
    { void* p; cudaGetSymbolAddress(&p, g_kin16); k16 = (__half*)p; }
    { void* p; cudaGetSymbolAddress(&p, g_vin16); v16 = (__half*)p; }
    { void* p; cudaGetSymbolAddress(&p, g_wq16);  wq16 = (__half*)p; }
    { void* p; cudaGetSymbolAddress(&p, g_wk16);  wk16 = (__half*)p; }
    { void* p; cudaGetSymbolAddress(&p, g_wv16);  wv16 = (__half*)p; }
    { void* p; cudaGetSymbolAddress(&p, g_wo16);  wo16 = (__half*)p; }

    cudaFuncSetAttribute(fused_attn_h, cudaFuncAttributeMaxDynamicSharedMemorySize,
                         FTOT_BYTES);

    cudaStream_t s2 = get_s2();
    cudaEvent_t evA = get_ev(0), evB = get_ev(1), evJoin = get_ev(2);

    const int M = Bc * Sc;                      // 4096
    dim3 thr(256);
    const size_t HALF4 = ATTN_E / 8;

    prep_h<<<dim3(256, 1, 7), thr>>>(
        (const float4*)query, (const float4*)key, (const float4*)value,
        (const float4*)Wq, (const float4*)Wk, (const float4*)Wv, (const float4*)Wo,
        q16, k16, v16, wq16, wk16, wv16, wo16);

    qkv_gemm_h<<<dim3(Dc / 128, M / 128, 3), thr>>>(q16, k16, v16,
                                                    wq16, bq, wk16, bk, wv16, bv,
                                                    Q16, K16, V16);

    v_transpose<<<dim3(Sc / 64, 1, BHc), thr>>>(V16, Vt);

    // ---- fused attention split into two half-grids ----
    dim3 gfa(Sc / 128, BHc / 2);                // (16, 16)

    fused_attn_h<<<gfa, thr, FTOT_BYTES>>>(Q16, K16, Vt, attn, isum, ctx16, 0);
    cudaEventRecord(evA, 0);

    fused_attn_h<<<gfa, thr, FTOT_BYTES>>>(Q16, K16, Vt, attn, isum, ctx16, BHc / 2);
    cudaEventRecord(evB, 0);

    // s2: norm first half while second half of fused runs on s0
    cudaStreamWaitEvent(s2, evA, 0);
    norm_k<<<2368, 256, 0, s2>>>((float4*)attn, isum, 0, HALF4);

    // out-projection on s0
    outproj_h<<<dim3(Dc / 128, M / 128), thr>>>(ctx16, wo16, bo, out);

    // s2: norm second half, overlapping out-proj
    cudaStreamWaitEvent(s2, evB, 0);
    norm_k<<<2368, 256, 0, s2>>>((float4*)attn, isum, HALF4, HALF4);

    cudaEventRecord(evJoin, s2);
    cudaStreamWaitEvent(0, evJoin, 0);
}